// round 3
// baseline (speedup 1.0000x reference)
#include <cuda_runtime.h>
#include <cuda_bf16.h>
#include <cstdint>

// Fixed problem shapes
#define H_DIM 64
#define W_DIM 176
#define D_DIM 112
#define D4    (D_DIM / 4)          // 28 float4 chunks per feature row
#define CH    (H_DIM - 1)          // 63 cell rows
#define CW    (W_DIM - 1)          // 175 cell cols
#define NCELLS (CH * CW)           // 11025
#define NSUB   4                   // sub-counters per cell (atomic contention /4)
#define SUBCAP 64                  // slots per sub-list
#define CELLCAP (NSUB * SUBCAP)    // 256 points per cell capacity

// Scratch (device globals; no runtime allocation allowed)
__device__ int    g_counts[NCELLS * NSUB];            // 176 KB
__device__ int    g_ib[NCELLS * CELLCAP];             // 11.3 MB point indices
__device__ float2 g_wb[NCELLS * CELLCAP];             // 22.6 MB (wx, wy)

__device__ __forceinline__ void red_add_v4(float* addr, float a, float b, float c, float d) {
    asm volatile("red.global.add.v4.f32 [%0], {%1, %2, %3, %4};"
                 :: "l"(addr), "f"(a), "f"(b), "f"(c), "f"(d)
                 : "memory");
}

// ---------------------------------------------------------------- pass 1: fused bin + weight precompute
__global__ __launch_bounds__(256)
void bin_kernel(const float2* __restrict__ pos,
                const float4* __restrict__ feat,
                float* __restrict__ out,
                int n)
{
    const int i = blockIdx.x * blockDim.x + threadIdx.x;
    if (i >= n) return;

    const float2 p = pos[i];
    const float xf = floorf(p.x);
    const float yf = floorf(p.y);
    const int cx = min(max((int)xf, 0), CW - 1);
    const int cy = min(max((int)yf, 0), CH - 1);
    const float wx = p.x - xf;
    const float wy = p.y - yf;
    const int cell = cy * CW + cx;

    const int sub  = i & (NSUB - 1);
    const int slot = atomicAdd(&g_counts[cell * NSUB + sub], 1);

    if (slot < SUBCAP) {
        const int off = cell * CELLCAP + sub * SUBCAP + slot;
        g_ib[off] = i;
        g_wb[off] = make_float2(wx, wy);
    } else {
        // Overflow fallback (statistically never hit): direct scatter of this point.
        const float w00 = (1.0f - wy) * (1.0f - wx);
        const float w01 = (1.0f - wy) * wx;
        const float w10 = wy * (1.0f - wx);
        const float w11 = wy * wx;
        const float4* frow = feat + (size_t)i * D4;
        float* o00 = out + ((size_t)(cy * W_DIM + cx) * D_DIM);
        float* o01 = o00 + D_DIM;
        float* o10 = o00 + (size_t)W_DIM * D_DIM;
        float* o11 = o10 + D_DIM;
        for (int k = 0; k < D4; k++) {
            const float4 f = frow[k];
            red_add_v4(o00 + k*4, w00*f.x, w00*f.y, w00*f.z, w00*f.w);
            red_add_v4(o01 + k*4, w01*f.x, w01*f.y, w01*f.z, w01*f.w);
            red_add_v4(o10 + k*4, w10*f.x, w10*f.y, w10*f.z, w10*f.w);
            red_add_v4(o11 + k*4, w11*f.x, w11*f.y, w11*f.z, w11*f.w);
        }
    }
}

// ---------------------------------------------------------------- pass 2: warp-per-cell gather + tiny scatter
__global__ __launch_bounds__(256, 8)
void cell_kernel(const float4* __restrict__ feat,
                 float* __restrict__ out)
{
    const int warp = threadIdx.x >> 5;
    const int lane = threadIdx.x & 31;
    const int cell = blockIdx.x * 8 + warp;
    if (cell >= NCELLS) return;

    const int cy = cell / CW;
    const int cx = cell - cy * CW;

    float4 a00 = {0,0,0,0}, a01 = {0,0,0,0}, a10 = {0,0,0,0}, a11 = {0,0,0,0};
    int total = 0;
    const bool active = (lane < D4);

    #pragma unroll
    for (int s = 0; s < NSUB; s++) {
        const int cnt  = min(g_counts[cell * NSUB + s], SUBCAP);
        total += cnt;
        const int base = cell * CELLCAP + s * SUBCAP;

        int i = 0;
        // 4x software pipeline: indices+weights (warp-uniform broadcast loads),
        // then 4 feature rows in flight, then accumulate.
        for (; i + 3 < cnt; i += 4) {
            const int    i0 = g_ib[base + i + 0];
            const int    i1 = g_ib[base + i + 1];
            const int    i2 = g_ib[base + i + 2];
            const int    i3 = g_ib[base + i + 3];
            const float2 q0 = g_wb[base + i + 0];
            const float2 q1 = g_wb[base + i + 1];
            const float2 q2 = g_wb[base + i + 2];
            const float2 q3 = g_wb[base + i + 3];
            float4 f0 = {0,0,0,0}, f1 = {0,0,0,0}, f2 = {0,0,0,0}, f3 = {0,0,0,0};
            if (active) {
                f0 = feat[(size_t)i0 * D4 + lane];
                f1 = feat[(size_t)i1 * D4 + lane];
                f2 = feat[(size_t)i2 * D4 + lane];
                f3 = feat[(size_t)i3 * D4 + lane];
            }
            {
                const float w00 = (1.0f-q0.y)*(1.0f-q0.x), w01 = (1.0f-q0.y)*q0.x;
                const float w10 = q0.y*(1.0f-q0.x),        w11 = q0.y*q0.x;
                a00.x += w00*f0.x; a00.y += w00*f0.y; a00.z += w00*f0.z; a00.w += w00*f0.w;
                a01.x += w01*f0.x; a01.y += w01*f0.y; a01.z += w01*f0.z; a01.w += w01*f0.w;
                a10.x += w10*f0.x; a10.y += w10*f0.y; a10.z += w10*f0.z; a10.w += w10*f0.w;
                a11.x += w11*f0.x; a11.y += w11*f0.y; a11.z += w11*f0.z; a11.w += w11*f0.w;
            }
            {
                const float w00 = (1.0f-q1.y)*(1.0f-q1.x), w01 = (1.0f-q1.y)*q1.x;
                const float w10 = q1.y*(1.0f-q1.x),        w11 = q1.y*q1.x;
                a00.x += w00*f1.x; a00.y += w00*f1.y; a00.z += w00*f1.z; a00.w += w00*f1.w;
                a01.x += w01*f1.x; a01.y += w01*f1.y; a01.z += w01*f1.z; a01.w += w01*f1.w;
                a10.x += w10*f1.x; a10.y += w10*f1.y; a10.z += w10*f1.z; a10.w += w10*f1.w;
                a11.x += w11*f1.x; a11.y += w11*f1.y; a11.z += w11*f1.z; a11.w += w11*f1.w;
            }
            {
                const float w00 = (1.0f-q2.y)*(1.0f-q2.x), w01 = (1.0f-q2.y)*q2.x;
                const float w10 = q2.y*(1.0f-q2.x),        w11 = q2.y*q2.x;
                a00.x += w00*f2.x; a00.y += w00*f2.y; a00.z += w00*f2.z; a00.w += w00*f2.w;
                a01.x += w01*f2.x; a01.y += w01*f2.y; a01.z += w01*f2.z; a01.w += w01*f2.w;
                a10.x += w10*f2.x; a10.y += w10*f2.y; a10.z += w10*f2.z; a10.w += w10*f2.w;
                a11.x += w11*f2.x; a11.y += w11*f2.y; a11.z += w11*f2.z; a11.w += w11*f2.w;
            }
            {
                const float w00 = (1.0f-q3.y)*(1.0f-q3.x), w01 = (1.0f-q3.y)*q3.x;
                const float w10 = q3.y*(1.0f-q3.x),        w11 = q3.y*q3.x;
                a00.x += w00*f3.x; a00.y += w00*f3.y; a00.z += w00*f3.z; a00.w += w00*f3.w;
                a01.x += w01*f3.x; a01.y += w01*f3.y; a01.z += w01*f3.z; a01.w += w01*f3.w;
                a10.x += w10*f3.x; a10.y += w10*f3.y; a10.z += w10*f3.z; a10.w += w10*f3.w;
                a11.x += w11*f3.x; a11.y += w11*f3.y; a11.z += w11*f3.z; a11.w += w11*f3.w;
            }
        }
        // tail
        for (; i < cnt; i++) {
            const int    idx = g_ib[base + i];
            const float2 q   = g_wb[base + i];
            float4 f = {0,0,0,0};
            if (active) f = feat[(size_t)idx * D4 + lane];
            const float w00 = (1.0f-q.y)*(1.0f-q.x), w01 = (1.0f-q.y)*q.x;
            const float w10 = q.y*(1.0f-q.x),        w11 = q.y*q.x;
            a00.x += w00*f.x; a00.y += w00*f.y; a00.z += w00*f.z; a00.w += w00*f.w;
            a01.x += w01*f.x; a01.y += w01*f.y; a01.z += w01*f.z; a01.w += w01*f.w;
            a10.x += w10*f.x; a10.y += w10*f.y; a10.z += w10*f.z; a10.w += w10*f.w;
            a11.x += w11*f.x; a11.y += w11*f.y; a11.z += w11*f.z; a11.w += w11*f.w;
        }
    }

    if (total == 0 || !active) return;

    float* o00 = out + ((size_t)(cy * W_DIM + cx) * D_DIM + lane * 4);
    float* o01 = o00 + D_DIM;
    float* o10 = o00 + (size_t)W_DIM * D_DIM;
    float* o11 = o10 + D_DIM;
    red_add_v4(o00, a00.x, a00.y, a00.z, a00.w);
    red_add_v4(o01, a01.x, a01.y, a01.z, a01.w);
    red_add_v4(o10, a10.x, a10.y, a10.z, a10.w);
    red_add_v4(o11, a11.x, a11.y, a11.z, a11.w);
}

// ---------------------------------------------------------------- launch
extern "C" void kernel_launch(void* const* d_in, const int* in_sizes, int n_in,
                              void* d_out, int out_size)
{
    const float2* pos  = (const float2*)d_in[0];
    const float4* feat = (const float4*)d_in[1];
    float* out = (float*)d_out;
    const int n = in_sizes[0] / 2;

    void* counts_ptr = nullptr;
    cudaGetSymbolAddress(&counts_ptr, g_counts);

    cudaMemsetAsync(out, 0, (size_t)out_size * sizeof(float));
    cudaMemsetAsync(counts_ptr, 0, sizeof(int) * NCELLS * NSUB);

    bin_kernel<<<(n + 255) / 256, 256>>>(pos, feat, out, n);
    cell_kernel<<<(NCELLS + 7) / 8, 256>>>(feat, out);
}

// round 4
// speedup vs baseline: 2.1287x; 2.1287x over previous
#include <cuda_runtime.h>
#include <cuda_bf16.h>
#include <cstdint>

// Fixed problem shapes
#define H_DIM 64
#define W_DIM 176
#define D_DIM 112
#define D4    (D_DIM / 4)          // 28 float4 chunks per feature row
#define CH    (H_DIM - 1)          // 63 cell rows
#define CW    (W_DIM - 1)          // 175 cell cols
#define NCELLS (CH * CW)           // 11025
#define NSUB   4                   // sub-lists per cell == warps per CTA
#define SUBCAP 64                  // slots per sub-list
#define CELLCAP (NSUB * SUBCAP)

// Scratch (device globals; no runtime allocation allowed)
__device__ int    g_counts[NCELLS * NSUB];              // 176 KB (memset each run)
__device__ float4 g_meta[NCELLS * CELLCAP];             // 45 MB: (wx, wy, idx_bits, valid)

__device__ __forceinline__ void red_add_v4(float* addr, float a, float b, float c, float d) {
    asm volatile("red.global.add.v4.f32 [%0], {%1, %2, %3, %4};"
                 :: "l"(addr), "f"(a), "f"(b), "f"(c), "f"(d)
                 : "memory");
}

// ---------------------------------------------------------------- pass 1: fused bin + weight precompute
__global__ __launch_bounds__(256)
void bin_kernel(const float2* __restrict__ pos,
                const float4* __restrict__ feat,
                float* __restrict__ out,
                int n)
{
    const int i = blockIdx.x * blockDim.x + threadIdx.x;
    if (i >= n) return;

    const float2 p = pos[i];
    const float xf = floorf(p.x);
    const float yf = floorf(p.y);
    const int cx = min(max((int)xf, 0), CW - 1);
    const int cy = min(max((int)yf, 0), CH - 1);
    const float wx = p.x - xf;
    const float wy = p.y - yf;
    const int cell = cy * CW + cx;

    const int sub  = i & (NSUB - 1);
    const int slot = atomicAdd(&g_counts[cell * NSUB + sub], 1);

    if (slot < SUBCAP) {
        g_meta[(cell * NSUB + sub) * SUBCAP + slot] =
            make_float4(wx, wy, __int_as_float(i), 1.0f);
    } else {
        // Overflow fallback (statistically never hit): direct scatter of this point.
        const float w00 = (1.0f - wy) * (1.0f - wx);
        const float w01 = (1.0f - wy) * wx;
        const float w10 = wy * (1.0f - wx);
        const float w11 = wy * wx;
        const float4* frow = feat + (size_t)i * D4;
        float* o00 = out + ((size_t)(cy * W_DIM + cx) * D_DIM);
        float* o01 = o00 + D_DIM;
        float* o10 = o00 + (size_t)W_DIM * D_DIM;
        float* o11 = o10 + D_DIM;
        for (int k = 0; k < D4; k++) {
            const float4 f = frow[k];
            red_add_v4(o00 + k*4, w00*f.x, w00*f.y, w00*f.z, w00*f.w);
            red_add_v4(o01 + k*4, w01*f.x, w01*f.y, w01*f.z, w01*f.w);
            red_add_v4(o10 + k*4, w10*f.x, w10*f.y, w10*f.z, w10*f.w);
            red_add_v4(o11 + k*4, w11*f.x, w11*f.y, w11*f.z, w11*f.w);
        }
    }
}

// ---------------------------------------------------------------- pass 2: CTA-per-cell gather
// Warp w consumes sub-list w. Metadata staged once into smem; inner loop is
// pure feature-LDG + FMA with MLP 4 (padded entries carry valid=0).
__global__ __launch_bounds__(128)
void cell_kernel(const float4* __restrict__ feat,
                 float* __restrict__ out)
{
    const int cell = blockIdx.x;
    const int warp = threadIdx.x >> 5;
    const int lane = threadIdx.x & 31;

    // All 4 sub-counts with one int4 load (warp-uniform)
    const int4 c4 = *reinterpret_cast<const int4*>(&g_counts[cell * NSUB]);
    const int total = min(c4.x, SUBCAP) + min(c4.y, SUBCAP)
                    + min(c4.z, SUBCAP) + min(c4.w, SUBCAP);
    if (total == 0) return;

    const int cnt = min(warp == 0 ? c4.x : warp == 1 ? c4.y : warp == 2 ? c4.z : c4.w, SUBCAP);
    const int cnt_r = (cnt + 3) & ~3;          // rounded up; pads have valid=0

    __shared__ float4 smeta[NSUB][SUBCAP];     // 4 KB
    __shared__ float4 sred[NSUB][4][D4];       // 7 KB

    // Stage sub-list metadata: 2 coalesced LDG.128 per warp, pad with zeros.
    {
        const float4 z = make_float4(0.f, 0.f, 0.f, 0.f);
        const int base = (cell * NSUB + warp) * SUBCAP;
        smeta[warp][lane]      = (lane      < cnt) ? g_meta[base + lane]      : z;
        smeta[warp][lane + 32] = (lane + 32 < cnt) ? g_meta[base + lane + 32] : z;
    }
    __syncwarp();

    const bool active = (lane < D4);
    float4 a00 = {0,0,0,0}, a01 = {0,0,0,0}, a10 = {0,0,0,0}, a11 = {0,0,0,0};

    for (int i = 0; i < cnt_r; i += 4) {
        const float4 m0 = smeta[warp][i + 0];
        const float4 m1 = smeta[warp][i + 1];
        const float4 m2 = smeta[warp][i + 2];
        const float4 m3 = smeta[warp][i + 3];
        const int i0 = __float_as_int(m0.z);
        const int i1 = __float_as_int(m1.z);
        const int i2 = __float_as_int(m2.z);
        const int i3 = __float_as_int(m3.z);
        float4 f0 = {0,0,0,0}, f1 = {0,0,0,0}, f2 = {0,0,0,0}, f3 = {0,0,0,0};
        if (active) {
            f0 = feat[(size_t)i0 * D4 + lane];
            f1 = feat[(size_t)i1 * D4 + lane];
            f2 = feat[(size_t)i2 * D4 + lane];
            f3 = feat[(size_t)i3 * D4 + lane];
        }
        {
            const float u = (1.0f - m0.x) * m0.w, v = m0.x * m0.w;
            const float w00 = (1.0f - m0.y) * u, w01 = (1.0f - m0.y) * v;
            const float w10 = m0.y * u,          w11 = m0.y * v;
            a00.x += w00*f0.x; a00.y += w00*f0.y; a00.z += w00*f0.z; a00.w += w00*f0.w;
            a01.x += w01*f0.x; a01.y += w01*f0.y; a01.z += w01*f0.z; a01.w += w01*f0.w;
            a10.x += w10*f0.x; a10.y += w10*f0.y; a10.z += w10*f0.z; a10.w += w10*f0.w;
            a11.x += w11*f0.x; a11.y += w11*f0.y; a11.z += w11*f0.z; a11.w += w11*f0.w;
        }
        {
            const float u = (1.0f - m1.x) * m1.w, v = m1.x * m1.w;
            const float w00 = (1.0f - m1.y) * u, w01 = (1.0f - m1.y) * v;
            const float w10 = m1.y * u,          w11 = m1.y * v;
            a00.x += w00*f1.x; a00.y += w00*f1.y; a00.z += w00*f1.z; a00.w += w00*f1.w;
            a01.x += w01*f1.x; a01.y += w01*f1.y; a01.z += w01*f1.z; a01.w += w01*f1.w;
            a10.x += w10*f1.x; a10.y += w10*f1.y; a10.z += w10*f1.z; a10.w += w10*f1.w;
            a11.x += w11*f1.x; a11.y += w11*f1.y; a11.z += w11*f1.z; a11.w += w11*f1.w;
        }
        {
            const float u = (1.0f - m2.x) * m2.w, v = m2.x * m2.w;
            const float w00 = (1.0f - m2.y) * u, w01 = (1.0f - m2.y) * v;
            const float w10 = m2.y * u,          w11 = m2.y * v;
            a00.x += w00*f2.x; a00.y += w00*f2.y; a00.z += w00*f2.z; a00.w += w00*f2.w;
            a01.x += w01*f2.x; a01.y += w01*f2.y; a01.z += w01*f2.z; a01.w += w01*f2.w;
            a10.x += w10*f2.x; a10.y += w10*f2.y; a10.z += w10*f2.z; a10.w += w10*f2.w;
            a11.x += w11*f2.x; a11.y += w11*f2.y; a11.z += w11*f2.z; a11.w += w11*f2.w;
        }
        {
            const float u = (1.0f - m3.x) * m3.w, v = m3.x * m3.w;
            const float w00 = (1.0f - m3.y) * u, w01 = (1.0f - m3.y) * v;
            const float w10 = m3.y * u,          w11 = m3.y * v;
            a00.x += w00*f3.x; a00.y += w00*f3.y; a00.z += w00*f3.z; a00.w += w00*f3.w;
            a01.x += w01*f3.x; a01.y += w01*f3.y; a01.z += w01*f3.z; a01.w += w01*f3.w;
            a10.x += w10*f3.x; a10.y += w10*f3.y; a10.z += w10*f3.z; a10.w += w10*f3.w;
            a11.x += w11*f3.x; a11.y += w11*f3.y; a11.z += w11*f3.z; a11.w += w11*f3.w;
        }
    }

    // Cross-warp reduce through smem
    if (active) {
        sred[warp][0][lane] = a00;
        sred[warp][1][lane] = a01;
        sred[warp][2][lane] = a10;
        sred[warp][3][lane] = a11;
    }
    __syncthreads();

    // 112 threads: thread t -> corner t/28, chunk t%28. One RED.v4 each.
    const int t = threadIdx.x;
    if (t < 4 * D4) {
        const int c = t / D4;
        const int k = t - c * D4;
        const float4 v0 = sred[0][c][k], v1 = sred[1][c][k];
        const float4 v2 = sred[2][c][k], v3 = sred[3][c][k];
        const float vx = v0.x + v1.x + v2.x + v3.x;
        const float vy = v0.y + v1.y + v2.y + v3.y;
        const float vz = v0.z + v1.z + v2.z + v3.z;
        const float vw = v0.w + v1.w + v2.w + v3.w;
        const int cy = cell / CW;
        const int cx = cell - cy * CW;
        const int dy = c >> 1, dx = c & 1;
        float* addr = out + ((size_t)((cy + dy) * W_DIM + (cx + dx)) * D_DIM + k * 4);
        red_add_v4(addr, vx, vy, vz, vw);
    }
}

// ---------------------------------------------------------------- launch
extern "C" void kernel_launch(void* const* d_in, const int* in_sizes, int n_in,
                              void* d_out, int out_size)
{
    const float2* pos  = (const float2*)d_in[0];
    const float4* feat = (const float4*)d_in[1];
    float* out = (float*)d_out;
    const int n = in_sizes[0] / 2;

    void* counts_ptr = nullptr;
    cudaGetSymbolAddress(&counts_ptr, g_counts);

    cudaMemsetAsync(out, 0, (size_t)out_size * sizeof(float));
    cudaMemsetAsync(counts_ptr, 0, sizeof(int) * NCELLS * NSUB);

    bin_kernel<<<(n + 255) / 256, 256>>>(pos, feat, out, n);
    cell_kernel<<<NCELLS, 128>>>(feat, out);
}